// round 2
// baseline (speedup 1.0000x reference)
#include <cuda_runtime.h>
#include <cstddef>

// Problem constants
#define BB 2
#define NN 256
#define DD 256
#define JC 128          // j-chunk rows of H processed per phase
#define HSTRIDE 132     // padded stride (floats) for H^T tile rows (16B aligned, odd/32-bank-friendly-ish)

// Scratch for projected x (allowed: __device__ globals, no allocation)
__device__ float g_xi[BB * NN * DD];
__device__ float g_xj[BB * NN * DD];

// ---------------------------------------------------------------------------
// Kernel 1: xi = x @ w_vi, xj = x @ w_vj   (one CTA per (b,n) row)
// ---------------------------------------------------------------------------
__global__ void __launch_bounds__(256) proj_kernel(const float* __restrict__ x,
                                                   const float* __restrict__ w_vi,
                                                   const float* __restrict__ w_vj)
{
    __shared__ float sX[DD];
    const int row = blockIdx.x;      // b*NN + n
    const int k = threadIdx.x;
    sX[k] = x[row * DD + k];
    __syncthreads();

    float ai = 0.f, aj = 0.f;
#pragma unroll 8
    for (int d = 0; d < DD; d++) {
        const float xv = sX[d];
        ai = fmaf(xv, w_vi[d * DD + k], ai);
        aj = fmaf(xv, w_vj[d * DD + k], aj);
    }
    g_xi[row * DD + k] = ai;
    g_xj[row * DD + k] = aj;
}

// ---------------------------------------------------------------------------
// Kernel 2: fused H build + AH accumulation + new_alpha GEMM + new_x
// One CTA per (b,i). 256 threads.
//
// smem:
//   sHT  [256][HSTRIDE]  : H^T chunk, sHT[d][jj] for jj in [0,128)
//   sW   [32][256]       : w_alpha K-chunk (rows d, cols k)
//   sXi  [256], sAH [256], sAdj [256]
// ---------------------------------------------------------------------------
__global__ void __launch_bounds__(256, 1) main_kernel(
    const float* __restrict__ alpha,
    const float* __restrict__ adj,
    const float* __restrict__ w_alpha,
    const float* __restrict__ bias_h,
    const float* __restrict__ w_node,
    float* __restrict__ out_x,        // [BB*NN*DD]
    float* __restrict__ out_alpha)    // [BB*NN*NN*DD]
{
    extern __shared__ float smem[];
    float* sHT  = smem;                       // 256*HSTRIDE
    float* sW   = sHT + 256 * HSTRIDE;        // 32*256
    float* sXi  = sW + 32 * 256;              // 256
    float* sAH  = sXi + 256;                  // 256
    float* sAdj = sAH + 256;                  // 256

    const int bi  = blockIdx.x;               // b*NN + i
    const int tid = threadIdx.x;
    const int b   = bi >> 8;

    sXi[tid]  = g_xi[bi * DD + tid];
    sAdj[tid] = adj[bi * NN + tid];
    __syncthreads();

    const int tk = tid & 15;   // k-group: thread covers k = tk*4 + 64*q, q in [0,4)
    const int tj = tid >> 4;   // j-group: thread covers j = j0 + tj*8 + r, r in [0,8)

    float ah = 0.f;            // AH[d = tid] accumulator across all j
    const float* alpha_base = alpha + (size_t)bi * NN * DD;

    for (int jc = 0; jc < 2; jc++) {
        const int j0 = jc * JC;

        // ---- Phase A: build H^T chunk into smem, fuse adj-weighted reduce ----
        {
            const float* aP  = alpha_base + (size_t)j0 * DD + tid;   // alpha[b,i,j0+jj,tid]
            const float* xjP = g_xj + ((size_t)b * NN + j0) * DD + tid;
            const float* bP  = bias_h + (size_t)j0 * DD + tid;
            const float  xiv = sXi[tid];
            float* hRow = sHT + tid * HSTRIDE;   // row d = tid
#pragma unroll 4
            for (int jj = 0; jj < JC; jj++) {
                const float v = aP[jj * DD] + xjP[jj * DD] + bP[jj * DD] + xiv;
                const float h = fmaxf(v, 0.f);
                hRow[jj] = h;
                ah = fmaf(sAdj[j0 + jj], h, ah);
            }
        }
        __syncthreads();

        // ---- Phase B: C[128 x 256] = H_chunk @ w_alpha, reg-tiled 8x16 ----
        float acc[8][16];
#pragma unroll
        for (int r = 0; r < 8; r++)
#pragma unroll
            for (int c = 0; c < 16; c++) acc[r][c] = 0.f;

        for (int dc = 0; dc < 8; dc++) {
            // stage w_alpha rows [dc*32, dc*32+32) into sW (coalesced float4)
            {
                const float4* wsrc = (const float4*)(w_alpha + dc * 32 * DD);
                float4* wdst = (float4*)sW;
#pragma unroll
                for (int i2 = 0; i2 < 8; i2++)
                    wdst[i2 * 256 + tid] = wsrc[i2 * 256 + tid];
            }
            __syncthreads();

            const float* hBase = sHT + (dc * 32) * HSTRIDE + tj * 8;
#pragma unroll 2
            for (int dd = 0; dd < 32; dd++) {
                const float* hR = hBase + dd * HSTRIDE;
                const float4 a0 = *(const float4*)(hR);
                const float4 a1 = *(const float4*)(hR + 4);
                const float a[8] = {a0.x, a0.y, a0.z, a0.w, a1.x, a1.y, a1.z, a1.w};
                const float* wR = sW + dd * 256 + tk * 4;
#pragma unroll
                for (int q = 0; q < 4; q++) {
                    const float4 bv = *(const float4*)(wR + q * 64);
#pragma unroll
                    for (int r = 0; r < 8; r++) {
                        acc[r][q * 4 + 0] = fmaf(a[r], bv.x, acc[r][q * 4 + 0]);
                        acc[r][q * 4 + 1] = fmaf(a[r], bv.y, acc[r][q * 4 + 1]);
                        acc[r][q * 4 + 2] = fmaf(a[r], bv.z, acc[r][q * 4 + 2]);
                        acc[r][q * 4 + 3] = fmaf(a[r], bv.w, acc[r][q * 4 + 3]);
                    }
                }
            }
            __syncthreads();
        }

        // ---- Phase C: epilogue — relu + store new_alpha chunk ----
        {
            float* oBase = out_alpha + ((size_t)bi * NN + j0) * DD;
#pragma unroll
            for (int r = 0; r < 8; r++) {
                float* oRow = oBase + (size_t)(tj * 8 + r) * DD;
#pragma unroll
                for (int q = 0; q < 4; q++) {
                    float4 v;
                    v.x = fmaxf(acc[r][q * 4 + 0], 0.f);
                    v.y = fmaxf(acc[r][q * 4 + 1], 0.f);
                    v.z = fmaxf(acc[r][q * 4 + 2], 0.f);
                    v.w = fmaxf(acc[r][q * 4 + 3], 0.f);
                    *(float4*)(oRow + tk * 4 + q * 64) = v;
                }
            }
        }
    }

    // ---- Phase D: new_x[bi, k] = relu(AH @ w_node) ----
    sAH[tid] = ah;
    __syncthreads();
    float acc2 = 0.f;
    const float* wn = w_node + tid;
#pragma unroll 8
    for (int d = 0; d < DD; d++)
        acc2 = fmaf(sAH[d], wn[d * DD], acc2);
    out_x[bi * DD + tid] = fmaxf(acc2, 0.f);
}

// ---------------------------------------------------------------------------
// Launch
// Inputs (metadata order): x, alpha, adj, w_alpha, w_vi, w_vj, bias_h, w_node
// Output: new_x (131072 floats) then new_alpha (33554432 floats)
// ---------------------------------------------------------------------------
extern "C" void kernel_launch(void* const* d_in, const int* in_sizes, int n_in,
                              void* d_out, int out_size)
{
    const float* x       = (const float*)d_in[0];
    const float* alpha   = (const float*)d_in[1];
    const float* adj     = (const float*)d_in[2];
    const float* w_alpha = (const float*)d_in[3];
    const float* w_vi    = (const float*)d_in[4];
    const float* w_vj    = (const float*)d_in[5];
    const float* bias_h  = (const float*)d_in[6];
    const float* w_node  = (const float*)d_in[7];

    float* out       = (float*)d_out;
    float* out_x     = out;                     // new_x first (tuple order)
    float* out_alpha = out + BB * NN * DD;      // then new_alpha

    const int smem_bytes = (256 * HSTRIDE + 32 * 256 + 3 * 256) * (int)sizeof(float); // 171008
    cudaFuncSetAttribute(main_kernel, cudaFuncAttributeMaxDynamicSharedMemorySize, smem_bytes);

    proj_kernel<<<BB * NN, 256>>>(x, w_vi, w_vj);
    main_kernel<<<BB * NN, 256, smem_bytes>>>(alpha, adj, w_alpha, bias_h, w_node,
                                              out_x, out_alpha);
}

// round 4
// speedup vs baseline: 1.6885x; 1.6885x over previous
#include <cuda_runtime.h>
#include <cuda_bf16.h>
#include <cstdint>
#include <cstddef>

// ---------------------------------------------------------------------------
// Problem: B=2, N=256, D=256
//   xi = x@w_vi ; xj = x@w_vj
//   H[b,i,j,:] = relu(xi[b,i,:] + xj[b,j,:] + alpha[b,i,j,:] + bias_h[j,:])
//   AH[b,i,:]  = sum_j adj[b,i,j] * H[b,i,j,:]
//   new_x      = relu(AH @ w_node)
//   new_alpha  = relu(H @ w_alpha)          <- dominant GEMM, bf16x3 on mma.sync
// ---------------------------------------------------------------------------
#define BB 2
#define NN 256
#define DD 256

// ---------------------------------------------------------------------------
// Warp MMA helpers (sm_80+ PTX, works on plain sm_100)
// ---------------------------------------------------------------------------
__device__ __forceinline__ uint32_t smem_u32(const void* p) {
    uint32_t a;
    asm("{ .reg .u64 t; cvta.to.shared.u64 t, %1; cvt.u32.u64 %0, t; }" : "=r"(a) : "l"(p));
    return a;
}
__device__ __forceinline__ void ldsm_x4(uint32_t* r, uint32_t addr) {
    asm volatile("ldmatrix.sync.aligned.m8n8.x4.shared.b16 {%0,%1,%2,%3}, [%4];"
                 : "=r"(r[0]), "=r"(r[1]), "=r"(r[2]), "=r"(r[3]) : "r"(addr));
}
__device__ __forceinline__ void ldsm_x2(uint32_t* r, uint32_t addr) {
    asm volatile("ldmatrix.sync.aligned.m8n8.x2.shared.b16 {%0,%1}, [%2];"
                 : "=r"(r[0]), "=r"(r[1]) : "r"(addr));
}
__device__ __forceinline__ void mma_bf16(float* c, const uint32_t* a, const uint32_t* b) {
    asm volatile(
        "mma.sync.aligned.m16n8k16.row.col.f32.bf16.bf16.f32 "
        "{%0,%1,%2,%3}, {%4,%5,%6,%7}, {%8,%9}, {%0,%1,%2,%3};"
        : "+f"(c[0]), "+f"(c[1]), "+f"(c[2]), "+f"(c[3])
        : "r"(a[0]), "r"(a[1]), "r"(a[2]), "r"(a[3]), "r"(b[0]), "r"(b[1]));
}

// ---------------------------------------------------------------------------
// Device scratch (no allocation allowed)
// ---------------------------------------------------------------------------
__device__ float g_xi[BB * NN * DD];
__device__ float g_xj[BB * NN * DD];
// w_alpha split into bf16 hi/lo, k-chunked layout: [ks=d/16][n][kl=d%16]
// element index = ks*4096 + n*16 + kl ; as uint4: 8192 entries each
__device__ uint4 g_wB_hi[8192];
__device__ uint4 g_wB_lo[8192];

// ---------------------------------------------------------------------------
// SMEM layout (bytes)
//   sA: H tile [128 j][256 d] bf16, row stride 528B (264 bf16) -> 67584B each
//   sB: per-buf { hi [256 n][24 bf16] , lo [...] } = 24576B per buf, 2 bufs
// ---------------------------------------------------------------------------
#define A_STRIDE 528
#define SM_AHI 0
#define SM_ALO 67584
#define SM_B   135168
#define SB_BUF_STRIDE 24576
#define SB_LO_OFF 12288
#define SM_XI  184320
#define SM_ADJ 185344
#define SM_RED 186368          // 512 floats
#define SMEM_BYTES 188416

// ---------------------------------------------------------------------------
// Kernel 1: xi = x @ w_vi, xj = x @ w_vj
// ---------------------------------------------------------------------------
__global__ void __launch_bounds__(256) proj_kernel(const float* __restrict__ x,
                                                   const float* __restrict__ w_vi,
                                                   const float* __restrict__ w_vj)
{
    __shared__ float sX[DD];
    const int row = blockIdx.x;
    const int k = threadIdx.x;
    sX[k] = x[row * DD + k];
    __syncthreads();
    float ai = 0.f, aj = 0.f;
#pragma unroll 8
    for (int d = 0; d < DD; d++) {
        const float xv = sX[d];
        ai = fmaf(xv, w_vi[d * DD + k], ai);
        aj = fmaf(xv, w_vj[d * DD + k], aj);
    }
    g_xi[row * DD + k] = ai;
    g_xj[row * DD + k] = aj;
}

// ---------------------------------------------------------------------------
// Kernel 2: split w_alpha into bf16 hi/lo, k-chunked [ks][n][kl] layout
// ---------------------------------------------------------------------------
__global__ void __launch_bounds__(256) wconv_kernel(const float* __restrict__ w_alpha)
{
    const int idx = blockIdx.x * 256 + threadIdx.x;   // d*256 + n
    const int d = idx >> 8;
    const int n = idx & 255;
    const float v = w_alpha[idx];
    const __nv_bfloat16 hi = __float2bfloat16(v);
    const __nv_bfloat16 lo = __float2bfloat16(v - __bfloat162float(hi));
    const int pos = ((d >> 4) << 12) + (n << 4) + (d & 15);
    ((__nv_bfloat16*)g_wB_hi)[pos] = hi;
    ((__nv_bfloat16*)g_wB_lo)[pos] = lo;
}

// ---------------------------------------------------------------------------
// Main kernel building blocks
// ---------------------------------------------------------------------------

// Build H tile rows [j0, j0+128) as bf16 hi/lo into sA; fuse adj-weighted sums.
// Thread -> d-pair (tid&127)*2, j parity tid>>7 (step 2).
__device__ __forceinline__ void build_A(char* smem, const float* __restrict__ alpha_base,
                                        const float* __restrict__ xjB,
                                        const float* __restrict__ biasB,
                                        int j0, int tid, float& ah0, float& ah1)
{
    const float* sXi  = (const float*)(smem + SM_XI);
    const float* sAdj = (const float*)(smem + SM_ADJ);
    const int d0 = (tid & 127) * 2;
    const int jstart = tid >> 7;
    const float xi0 = sXi[d0], xi1 = sXi[d0 + 1];
    char* aHiB = smem + SM_AHI + d0 * 2;
    char* aLoB = smem + SM_ALO + d0 * 2;
#pragma unroll 4
    for (int jj = jstart; jj < 128; jj += 2) {
        const size_t off = (size_t)(j0 + jj) * DD + d0;
        const float2 av = *(const float2*)(alpha_base + off);
        const float2 xv = *(const float2*)(xjB + off);
        const float2 bv = *(const float2*)(biasB + off);
        const float h0 = fmaxf(av.x + xv.x + bv.x + xi0, 0.f);
        const float h1 = fmaxf(av.y + xv.y + bv.y + xi1, 0.f);
        const float aw = sAdj[j0 + jj];
        ah0 = fmaf(aw, h0, ah0);
        ah1 = fmaf(aw, h1, ah1);
        const __nv_bfloat16 hh0 = __float2bfloat16(h0);
        const __nv_bfloat16 hh1 = __float2bfloat16(h1);
        const __nv_bfloat16 hl0 = __float2bfloat16(h0 - __bfloat162float(hh0));
        const __nv_bfloat16 hl1 = __float2bfloat16(h1 - __bfloat162float(hh1));
        const uint32_t hp = ((uint32_t)__bfloat16_as_ushort(hh1) << 16) | __bfloat16_as_ushort(hh0);
        const uint32_t lp = ((uint32_t)__bfloat16_as_ushort(hl1) << 16) | __bfloat16_as_ushort(hl0);
        *(uint32_t*)(aHiB + jj * A_STRIDE) = hp;
        *(uint32_t*)(aLoB + jj * A_STRIDE) = lp;
    }
}

// Stage B k-chunk ks (hi+lo, 256 n x 16 k) into sB buf. 32B per thread, coalesced.
__device__ __forceinline__ void stageB(char* smem, int ks, int buf, int tid)
{
    const uint4* sh = g_wB_hi + ks * 512 + tid * 2;
    const uint4* sl = g_wB_lo + ks * 512 + tid * 2;
    const uint4 h0 = sh[0], h1 = sh[1];
    const uint4 l0 = sl[0], l1 = sl[1];
    char* bh = smem + SM_B + buf * SB_BUF_STRIDE + tid * 48;
    *(uint4*)(bh)      = h0;
    *(uint4*)(bh + 16) = h1;
    char* bl = bh + SB_LO_OFF;
    *(uint4*)(bl)      = l0;
    *(uint4*)(bl + 16) = l1;
}

// One 128x256 GEMM tile: acc += Hhi*Whi + Hlo*Whi + Hhi*Wlo over k=256 (16 ksteps)
__device__ __forceinline__ void mma_tile(char* smem, float acc[4][8][4],
                                         uint32_t aBaseHi, uint32_t bBase, int tid)
{
#pragma unroll
    for (int mb = 0; mb < 4; mb++)
#pragma unroll
        for (int nb = 0; nb < 8; nb++)
#pragma unroll
            for (int q = 0; q < 4; q++) acc[mb][nb][q] = 0.f;

    stageB(smem, 0, 0, tid);
    __syncthreads();

#pragma unroll 1
    for (int ks = 0; ks < 16; ks++) {
        const int buf = ks & 1;
        if (ks < 15) stageB(smem, ks + 1, buf ^ 1, tid);

        uint32_t Ah[4][4], Al[4][4];
        const uint32_t aOff = aBaseHi + ks * 32;
#pragma unroll
        for (int mb = 0; mb < 4; mb++) {
            ldsm_x4(Ah[mb], aOff + mb * (16 * A_STRIDE));
            ldsm_x4(Al[mb], aOff + mb * (16 * A_STRIDE) + (SM_ALO - SM_AHI));
        }
        const uint32_t bBuf = bBase + buf * SB_BUF_STRIDE;
#pragma unroll
        for (int nb = 0; nb < 8; nb++) {
            uint32_t Bh[2], Bl[2];
            ldsm_x2(Bh, bBuf + nb * 384);
            ldsm_x2(Bl, bBuf + nb * 384 + SB_LO_OFF);
#pragma unroll
            for (int mb = 0; mb < 4; mb++) {
                mma_bf16(acc[mb][nb], Ah[mb], Bh);
                mma_bf16(acc[mb][nb], Al[mb], Bh);
                mma_bf16(acc[mb][nb], Ah[mb], Bl);
            }
        }
        __syncthreads();
    }
}

// Relu + store one tile's accumulators
__device__ __forceinline__ void epilogue(const float acc[4][8][4], float* __restrict__ out_alpha,
                                         size_t bi, int j0, int rg, int cg, int lane)
{
    const int r0 = rg * 64 + (lane >> 2);
    const int c0 = cg * 64 + (lane & 3) * 2;
#pragma unroll
    for (int mb = 0; mb < 4; mb++) {
#pragma unroll
        for (int nb = 0; nb < 8; nb++) {
            float* base = out_alpha + ((size_t)bi * NN + j0 + r0 + mb * 16) * DD + c0 + nb * 8;
            float2 v0, v1;
            v0.x = fmaxf(acc[mb][nb][0], 0.f);
            v0.y = fmaxf(acc[mb][nb][1], 0.f);
            v1.x = fmaxf(acc[mb][nb][2], 0.f);
            v1.y = fmaxf(acc[mb][nb][3], 0.f);
            *(float2*)base = v0;
            *(float2*)(base + 8 * DD) = v1;
        }
    }
}

__global__ void __launch_bounds__(256, 1) main_kernel(
    const float* __restrict__ alpha,
    const float* __restrict__ adj,
    const float* __restrict__ bias_h,
    const float* __restrict__ w_node,
    float* __restrict__ out_x,
    float* __restrict__ out_alpha)
{
    extern __shared__ char smem[];
    const uint32_t sb = smem_u32(smem);
    const int tid  = threadIdx.x;
    const int wid  = tid >> 5;
    const int lane = tid & 31;
    const int rg = wid & 1;        // row-group (64 rows)
    const int cg = wid >> 1;       // col-group (64 cols)
    const size_t bi = blockIdx.x;  // b*NN + i
    const int b = (int)(bi >> 8);

    ((float*)(smem + SM_XI))[tid]  = g_xi[bi * DD + tid];
    ((float*)(smem + SM_ADJ))[tid] = adj[bi * NN + tid];
    __syncthreads();

    const float* alpha_base = alpha + bi * (size_t)NN * DD;
    const float* xjB = g_xj + (size_t)b * NN * DD;

    // per-thread ldmatrix base addresses
    const uint32_t aBaseHi = sb + SM_AHI + (uint32_t)(rg * 64 + (lane & 15)) * A_STRIDE
                           + (uint32_t)(lane >> 4) * 16;
    const uint32_t bBase = sb + SM_B + (uint32_t)(cg * 64 + (lane & 7)) * 48
                         + (uint32_t)((lane >> 3) & 1) * 16;

    float ah0 = 0.f, ah1 = 0.f;
    float acc[4][8][4];

    // ---- tile 0 ----
    build_A(smem, alpha_base, xjB, bias_h, 0, tid, ah0, ah1);
    __syncthreads();
    mma_tile(smem, acc, aBaseHi, bBase, tid);
    epilogue(acc, out_alpha, bi, 0, rg, cg, lane);

    // ---- tile 1 (sA free after mma_tile's final sync) ----
    build_A(smem, alpha_base, xjB, bias_h, 128, tid, ah0, ah1);
    {   // publish adj-weighted partial sums
        float* red = (float*)(smem + SM_RED);
        const int d0 = (tid & 127) * 2;
        const int p = tid >> 7;
        red[p * 256 + d0]     = ah0;
        red[p * 256 + d0 + 1] = ah1;
    }
    __syncthreads();
    mma_tile(smem, acc, aBaseHi, bBase, tid);
    epilogue(acc, out_alpha, bi, 128, rg, cg, lane);

    // ---- new_x ----
    {
        const float* red = (const float*)(smem + SM_RED);
        float acc2 = 0.f;
#pragma unroll 8
        for (int d = 0; d < DD; d++)
            acc2 = fmaf(red[d] + red[256 + d], w_node[d * DD + tid], acc2);
        out_x[bi * DD + tid] = fmaxf(acc2, 0.f);
    }
}

// ---------------------------------------------------------------------------
// Launch. Inputs: x, alpha, adj, w_alpha, w_vi, w_vj, bias_h, w_node
// Output: new_x (131072 f32) then new_alpha (33554432 f32)
// ---------------------------------------------------------------------------
extern "C" void kernel_launch(void* const* d_in, const int* in_sizes, int n_in,
                              void* d_out, int out_size)
{
    const float* x       = (const float*)d_in[0];
    const float* alpha   = (const float*)d_in[1];
    const float* adj     = (const float*)d_in[2];
    const float* w_alpha = (const float*)d_in[3];
    const float* w_vi    = (const float*)d_in[4];
    const float* w_vj    = (const float*)d_in[5];
    const float* bias_h  = (const float*)d_in[6];
    const float* w_node  = (const float*)d_in[7];

    float* out       = (float*)d_out;
    float* out_x     = out;
    float* out_alpha = out + BB * NN * DD;

    static bool attr_set = false;
    if (!attr_set) {
        cudaFuncSetAttribute(main_kernel, cudaFuncAttributeMaxDynamicSharedMemorySize, SMEM_BYTES);
        attr_set = true;
    }

    proj_kernel<<<BB * NN, 256>>>(x, w_vi, w_vj);
    wconv_kernel<<<256, 256>>>(w_alpha);
    main_kernel<<<BB * NN, 256, SMEM_BYTES>>>(alpha, adj, bias_h, w_node, out_x, out_alpha);
}